// round 16
// baseline (speedup 1.0000x reference)
#include <cuda_runtime.h>

// packed f32x2 FMA (PTX-only; ptxas never emits FFMA2 from C++)
#define FMA2(d, a, b, c) \
    asm("fma.rn.f32x2 %0, %1, %2, %3;" : "=l"(d) : "l"(a), "l"(b), "l"(c))

namespace cfg {
constexpr int H = 224, Wd = 224, C = 32, O = 32;
constexpr int TLW = 32, TLH = 16;     // output tile
constexpr int CCH = 8;                // channels per stage (4 stages; checkpoint after 2)
constexpr int TR  = 18;               // input rows per channel (16 + halo)
constexpr int S2  = 34;               // float2/row: (v,v) dup, cols x0-1 .. x0+32
constexpr int BUF2 = CCH * TR * S2;   // 4896 float2 per input buffer
constexpr int SMEM_BYTES = 2 * BUF2 * 8;  // 78,336 B double-buffered -> 2 blocks/SM
constexpr int KW = C * 9;             // 288 taps per output channel
}

// weights as (o, o+16) channel pairs: c_w[k*16 + op] = (W[op][k], W[op+16][k])
// 288*16 float2 = 36,864 B -> fits the constant bank. One LDC.128 feeds 2 pairs.
__device__ float2 g_wtmp[cfg::KW * 16];
__constant__ float2 c_w[cfg::KW * 16];

__global__ void weight_pack_kernel(const float* __restrict__ W)
{
    int i = blockIdx.x * 256 + threadIdx.x;
    if (i < cfg::KW * 16) {
        int k = i >> 4, op = i & 15;
        g_wtmp[i] = make_float2(W[op * cfg::KW + k], W[(op + 16) * cfg::KW + k]);
    }
}

// 4B cp.async with zero-fill for OOB (src redirected to a safe address when !ok)
__device__ __forceinline__ void cpa4(unsigned dst, const float* src, bool ok)
{
    int sz = ok ? 4 : 0;
    asm volatile("cp.async.ca.shared.global [%0], [%1], 4, %2;"
                 :: "r"(dst), "l"(src), "r"(sz));
}

__global__ __launch_bounds__(512, 2)
void conv_early_kernel(const float* __restrict__ x, float* __restrict__ out)
{
    using namespace cfg;
    extern __shared__ float2 sbuf[];     // two BUF2-sized (v,v)-dup buffers

    const int tid = threadIdx.x;
    const int wid = tid >> 5;            // warp 0..15 (staging role)
    const int l   = tid & 31;
    const int og  = tid >> 7;            // 0..3, warp-uniform: o = og*4+j (+16)
    const int pos = tid & 127;
    const int rr  = pos & 15;            // output row in tile
    const int xq  = pos >> 4;            // x quad: 4 px at x0 + 4*xq

    const int x0 = blockIdx.x * TLW;
    const int y0 = blockIdx.y * TLH;
    const int b  = blockIdx.z;
    const float* ximg = x + (size_t)b * C * H * Wd;
    const unsigned sbase = (unsigned)__cvta_generic_to_shared(sbuf);

    // staging role: warp w stages channel c = w/2, rows rbase = (w&1)*9 .. +8
    const int sc    = wid >> 1;
    const int rbase = (wid & 1) * 9;

    // tile: in2[c][r][j] = (v, v), v = x[ch][y0-1+r][x0-1+j], j = 0..33
    auto issue_stage = [&](int stage) {
        unsigned bufb = sbase + (unsigned)((stage & 1) * (BUF2 * 8));
        const float* cp = ximg + (size_t)(stage * CCH + sc) * H * Wd;
        #pragma unroll 3
        for (int k = 0; k < 9; k++) {
            int r  = rbase + k;
            int gy = y0 - 1 + r;
            bool rok = (unsigned)gy < (unsigned)H;
            const float* srow = cp + (size_t)gy * Wd + (x0 - 1);
            unsigned drow = bufb + (unsigned)(((sc * TR + r) * S2) * 8);
            bool ok0 = rok && ((unsigned)(x0 - 1 + l) < (unsigned)Wd);
            const float* s0 = ok0 ? srow + l : ximg;
            cpa4(drow + l * 8,     s0, ok0);        // duplicated halves
            cpa4(drow + l * 8 + 4, s0, ok0);
            if (l < 2) {
                int j = 32 + l;
                bool ok1 = rok && ((unsigned)(x0 + 31 + l) < (unsigned)Wd);
                const float* s1 = ok1 ? srow + j : ximg;
                cpa4(drow + j * 8,     s1, ok1);
                cpa4(drow + j * 8 + 4, s1, ok1);
            }
        }
        asm volatile("cp.async.commit_group;" ::: "memory");
    };

    unsigned long long acc[16];          // acc[j*4+pp] = (out[og*4+j], out[+16])
    #pragma unroll
    for (int i = 0; i < 16; i++) acc[i] = 0ull;
    unsigned mask = 0;                   // 32 early-terminate sign bits

    issue_stage(0);

    #pragma unroll 1
    for (int stage = 0; stage < 4; stage++) {
        asm volatile("cp.async.wait_group 0;" ::: "memory");
        __syncthreads();                 // stage tile visible; prior readers done
        if (stage < 3) issue_stage(stage + 1);   // overlap next load with compute

        const float2* cur = sbuf + (stage & 1) * BUF2;

        #pragma unroll 1
        for (int cl = 0; cl < CCH; cl++) {
            const int kb9 = (stage * CCH + cl) * 9;
            #pragma unroll
            for (int dy = 0; dy < 3; dy++) {
                const ulonglong2* ir = reinterpret_cast<const ulonglong2*>(
                    cur + (cl * TR + rr + dy) * S2 + 4 * xq);
                ulonglong2 A = ir[0], B = ir[1], Cv = ir[2];
                unsigned long long P[6] = {A.x, A.y, B.x, B.y, Cv.x, Cv.y};
                #pragma unroll
                for (int dx = 0; dx < 3; dx++) {
                    // 32B of (o,o+16) weight pairs: 2x LDC.128, zero PACKs
                    const ulonglong2* wk = reinterpret_cast<const ulonglong2*>(
                        c_w + ((kb9 + dy * 3 + dx) * 16 + og * 4));
                    ulonglong2 wa = wk[0], wb = wk[1];
                    unsigned long long wp[4] = {wa.x, wa.y, wb.x, wb.y};
                    #pragma unroll
                    for (int j = 0; j < 4; j++) {
                        #pragma unroll
                        for (int pp = 0; pp < 4; pp++)
                            FMA2(acc[j * 4 + pp], P[pp + dx], wp[j],
                                 acc[j * 4 + pp]);
                    }
                }
            }
        }

        if (stage == 1) {
            // 16-channel checkpoint: sign of partial sum per output element
            #pragma unroll
            for (int i = 0; i < 16; i++) {
                float lo = __uint_as_float((unsigned)(acc[i] & 0xffffffffull));
                float hi = __uint_as_float((unsigned)(acc[i] >> 32));
                mask |= (lo < 0.f ? 1u : 0u) << (2 * i);
                mask |= (hi < 0.f ? 1u : 0u) << (2 * i + 1);
            }
        }
    }

    // ---- epilogue: out = maskbit ? 0 : relu(full) ----
    const int gy  = y0 + rr;
    const int gx0 = x0 + 4 * xq;
    #pragma unroll
    for (int j = 0; j < 4; j++) {
        int o = og * 4 + j;
        float lo[4], hi[4];
        #pragma unroll
        for (int pp = 0; pp < 4; pp++) {
            unsigned long long a = acc[j * 4 + pp];
            float lv = __uint_as_float((unsigned)(a & 0xffffffffull));
            float hv = __uint_as_float((unsigned)(a >> 32));
            int bi = 2 * (j * 4 + pp);
            lo[pp] = ((mask >> bi)       & 1u) ? 0.f : fmaxf(lv, 0.f);
            hi[pp] = ((mask >> (bi + 1)) & 1u) ? 0.f : fmaxf(hv, 0.f);
        }
        float* p0 = out + (((size_t)b * O + o)      * H + gy) * Wd + gx0;
        float* p1 = out + (((size_t)b * O + o + 16) * H + gy) * Wd + gx0;
        *reinterpret_cast<float4*>(p0) = make_float4(lo[0], lo[1], lo[2], lo[3]);
        *reinterpret_cast<float4*>(p1) = make_float4(hi[0], hi[1], hi[2], hi[3]);
    }
}

extern "C" void kernel_launch(void* const* d_in, const int* in_sizes, int n_in,
                              void* d_out, int out_size)
{
    using namespace cfg;
    const float* x = (const float*)d_in[0];   // [32][32][224][224] f32
    const float* W = (const float*)d_in[1];   // [32][32][3][3] f32
    float* out = (float*)d_out;

    // pack (o,o+16) weight pairs, stage into constant bank
    weight_pack_kernel<<<(KW * 16 + 255) / 256, 256>>>(W);
    void* src = nullptr; void* dst = nullptr;
    cudaGetSymbolAddress(&src, g_wtmp);
    cudaGetSymbolAddress(&dst, c_w);
    cudaMemcpyAsync(dst, src, sizeof(float2) * KW * 16, cudaMemcpyDeviceToDevice);

    cudaFuncSetAttribute(conv_early_kernel,
                         cudaFuncAttributeMaxDynamicSharedMemorySize, SMEM_BYTES);
    dim3 grid(Wd / TLW, H / TLH, 32);         // 7 x 14 x 32
    conv_early_kernel<<<grid, 512, SMEM_BYTES>>>(x, out);
}

// round 17
// speedup vs baseline: 1.2584x; 1.2584x over previous
#include <cuda_runtime.h>

// packed f32x2 FMA + pack (PTX-only; ptxas never emits FFMA2 from C++)
#define FMA2(d, a, b, c) \
    asm("fma.rn.f32x2 %0, %1, %2, %3;" : "=l"(d) : "l"(a), "l"(b), "l"(c))
#define PACK2(d, lo, hi) \
    asm("mov.b64 %0, {%1, %2};" : "=l"(d) : "f"(lo), "f"(hi))

namespace cfg {
constexpr int H = 224, Wd = 224, C = 32, O = 32;
constexpr int TLW = 32, TLH = 16;     // output tile
constexpr int CCH = 8;                // channels per stage (4 stages; checkpoint after 2)
constexpr int TR  = 18;               // input rows per channel (16 + halo)
constexpr int S2  = 30;               // float2/row (cols 0..29 are all that's read)
constexpr int BUF2 = CCH * TR * S2;   // 4320 float2 per input buffer
constexpr int SMEM_BYTES = 2 * BUF2 * 8;  // 69,120 B double-buffered -> 2 blocks/SM
constexpr int KW = C * 9;             // 288 taps per output channel
}

// scalar weights transposed: c_ws[k*32 + o] = W[o][k], k = c*9+dy*3+dx  (36.9KB)
__device__ float g_wtmp[cfg::KW * 32];
__constant__ float c_ws[cfg::KW * 32];

__global__ void weight_pack_kernel(const float* __restrict__ W)
{
    int i = blockIdx.x * 256 + threadIdx.x;
    if (i < cfg::KW * 32) {
        int k = i >> 5, o = i & 31;
        g_wtmp[i] = W[o * cfg::KW + k];
    }
}

// 4B cp.async with zero-fill for OOB (src redirected to a safe address when !ok)
__device__ __forceinline__ void cpa4(unsigned dst, const float* src, bool ok)
{
    int sz = ok ? 4 : 0;
    asm volatile("cp.async.ca.shared.global [%0], [%1], 4, %2;"
                 :: "r"(dst), "l"(src), "r"(sz));
}

__global__ __launch_bounds__(512, 2)
void conv_early_kernel(const float* __restrict__ x, float* __restrict__ out)
{
    using namespace cfg;
    extern __shared__ float2 sbuf[];     // two BUF2-sized pixel-pair buffers

    const int tid = threadIdx.x;
    const int wid = tid >> 5;            // warp 0..15 (staging role)
    const int l   = tid & 31;
    const int og  = tid >> 6;            // 0..7, warp-uniform: o = og*4 .. og*4+3
    const int pos = tid & 63;
    const int rr  = pos & 15;            // output row in tile
    const int xb  = (pos >> 4) & 3;      // x block of 8 px

    const int x0 = blockIdx.x * TLW;
    const int y0 = blockIdx.y * TLH;
    const int b  = blockIdx.z;
    const float* ximg = x + (size_t)b * C * H * Wd;
    const unsigned sbase = (unsigned)__cvta_generic_to_shared(sbuf);

    // staging role: warp w stages channel c = w/2, rows rbase = (w&1)*9 .. +8
    const int sc    = wid >> 1;
    const int rbase = (wid & 1) * 9;

    // input tile: in2[c][r][col] = (t[col], t[col+4]), t[j] = x[ch][y0-1+r][x0-1+j]
    auto issue_stage = [&](int stage) {
        unsigned bufb = sbase + (unsigned)((stage & 1) * (BUF2 * 8));
        const float* cp = ximg + (size_t)(stage * CCH + sc) * H * Wd;
        if (l < 30) {
            #pragma unroll 3
            for (int k = 0; k < 9; k++) {
                int r  = rbase + k;
                int gy = y0 - 1 + r;
                bool rok = (unsigned)gy < (unsigned)H;
                const float* srow = cp + (size_t)gy * Wd + (x0 - 1);
                unsigned drow = bufb + (unsigned)(((sc * TR + r) * S2) * 8);
                bool okx = rok && ((unsigned)(x0 - 1 + l) < (unsigned)Wd);
                cpa4(drow + l * 8,     okx ? srow + l : ximg, okx);
                bool oky = rok && ((unsigned)(x0 + 3 + l) < (unsigned)Wd);
                cpa4(drow + l * 8 + 4, oky ? srow + l + 4 : ximg, oky);
            }
        }
        asm volatile("cp.async.commit_group;" ::: "memory");
    };

    unsigned long long acc[16];          // acc[o*4+pp] = (px pp, px pp+4), o local
    #pragma unroll
    for (int i = 0; i < 16; i++) acc[i] = 0ull;
    unsigned mask = 0;                   // 32 early-terminate sign bits

    const float4* cwf = reinterpret_cast<const float4*>(c_ws);

    issue_stage(0);

    #pragma unroll 1
    for (int stage = 0; stage < 4; stage++) {
        asm volatile("cp.async.wait_group 0;" ::: "memory");
        __syncthreads();                 // stage tile visible; prior readers done
        if (stage < 3) issue_stage(stage + 1);   // overlap next load with compute

        const float2* cur = sbuf + (stage & 1) * BUF2;

        #pragma unroll 2
        for (int cl = 0; cl < CCH; cl++) {
            const int kb9 = (stage * CCH + cl) * 9;
            #pragma unroll
            for (int dy = 0; dy < 3; dy++) {
                const ulonglong2* ir = reinterpret_cast<const ulonglong2*>(
                    cur + (cl * TR + rr + dy) * S2 + 8 * xb);
                ulonglong2 A = ir[0], B = ir[1], Cv = ir[2];
                unsigned long long P[6] = {A.x, A.y, B.x, B.y, Cv.x, Cv.y};
                #pragma unroll
                for (int dx = 0; dx < 3; dx++) {
                    float4 wa = cwf[(kb9 + dy * 3 + dx) * 8 + og];
                    unsigned long long wp[4];
                    PACK2(wp[0], wa.x, wa.x); PACK2(wp[1], wa.y, wa.y);
                    PACK2(wp[2], wa.z, wa.z); PACK2(wp[3], wa.w, wa.w);
                    #pragma unroll
                    for (int o = 0; o < 4; o++) {
                        #pragma unroll
                        for (int pp = 0; pp < 4; pp++)
                            FMA2(acc[o * 4 + pp], P[pp + dx], wp[o],
                                 acc[o * 4 + pp]);
                    }
                }
            }
        }

        if (stage == 1) {
            // 16-channel checkpoint: sign of partial sum per output element
            #pragma unroll
            for (int i = 0; i < 16; i++) {
                float lo = __uint_as_float((unsigned)(acc[i] & 0xffffffffull));
                float hi = __uint_as_float((unsigned)(acc[i] >> 32));
                mask |= (lo < 0.f ? 1u : 0u) << (2 * i);
                mask |= (hi < 0.f ? 1u : 0u) << (2 * i + 1);
            }
        }
    }

    // ---- epilogue: out = maskbit ? 0 : relu(full) ----
    const int gy  = y0 + rr;
    const int gx0 = x0 + 8 * xb;
    #pragma unroll
    for (int o = 0; o < 4; o++) {
        float lo[4], hi[4];
        #pragma unroll
        for (int pp = 0; pp < 4; pp++) {
            unsigned long long a = acc[o * 4 + pp];
            float lv = __uint_as_float((unsigned)(a & 0xffffffffull));
            float hv = __uint_as_float((unsigned)(a >> 32));
            int bi = 2 * (o * 4 + pp);
            lo[pp] = ((mask >> bi)       & 1u) ? 0.f : fmaxf(lv, 0.f);
            hi[pp] = ((mask >> (bi + 1)) & 1u) ? 0.f : fmaxf(hv, 0.f);
        }
        float* p = out + (((size_t)b * O + og * 4 + o) * H + gy) * Wd + gx0;
        *reinterpret_cast<float4*>(p)     = make_float4(lo[0], lo[1], lo[2], lo[3]);
        *reinterpret_cast<float4*>(p + 4) = make_float4(hi[0], hi[1], hi[2], hi[3]);
    }
}

extern "C" void kernel_launch(void* const* d_in, const int* in_sizes, int n_in,
                              void* d_out, int out_size)
{
    using namespace cfg;
    const float* x = (const float*)d_in[0];   // [32][32][224][224] f32
    const float* W = (const float*)d_in[1];   // [32][32][3][3] f32
    float* out = (float*)d_out;

    // transpose weights to [k][o] scalars, stage into constant bank
    weight_pack_kernel<<<(KW * 32 + 255) / 256, 256>>>(W);
    void* src = nullptr; void* dst = nullptr;
    cudaGetSymbolAddress(&src, g_wtmp);
    cudaGetSymbolAddress(&dst, c_ws);
    cudaMemcpyAsync(dst, src, sizeof(float) * KW * 32, cudaMemcpyDeviceToDevice);

    cudaFuncSetAttribute(conv_early_kernel,
                         cudaFuncAttributeMaxDynamicSharedMemorySize, SMEM_BYTES);
    dim3 grid(Wd / TLW, H / TLH, 32);         // 7 x 14 x 32
    conv_early_kernel<<<grid, 512, SMEM_BYTES>>>(x, out);
}